// round 6
// baseline (speedup 1.0000x reference)
#include <cuda_runtime.h>

#define BATCH 64
#define SEQ   1024
#define DMODEL 128
#define S134  134   // padded smem stride for 128-wide fp32 tiles (8-row step -> 16 banks apart)
#define SP66  66    // padded smem stride for 64-wide tiles

typedef unsigned long long u64;

// Scratch for projected q,k,v (allocation-free: __device__ globals)
__device__ float g_q[BATCH*SEQ*DMODEL];
__device__ float g_k[BATCH*SEQ*DMODEL];
__device__ float g_v[BATCH*SEQ*DMODEL];

// ---------- packed f32x2 helpers (SASS FFMA2: 2x fp32 FMA throughput) ----------
__device__ __forceinline__ void ffma2(u64 &d, u64 a, u64 b) {
    asm("fma.rn.f32x2 %0, %1, %2, %0;" : "+l"(d) : "l"(a), "l"(b));
}
__device__ __forceinline__ u64 pack2(float x, float y) {
    u64 r; asm("mov.b64 %0, {%1, %2};" : "=l"(r) : "f"(x), "f"(y)); return r;
}
__device__ __forceinline__ void unpack2(u64 v, float &x, float &y) {
    asm("mov.b64 {%0, %1}, %2;" : "=f"(x), "=f"(y) : "l"(v));
}
__device__ __forceinline__ u64 lds_pair(const float* p) {
    return *reinterpret_cast<const u64*>(p);
}
// deterministic fast tanh, ~1e-7 rel err
__device__ __forceinline__ float tanh_fast(float x) {
    float ax = fminf(fabsf(x), 20.0f);
    float e  = __expf(2.0f * ax);
    float t  = __fdividef(e - 1.0f, e + 1.0f);
    return copysignf(t, x);
}

// cooperative load 64x128 fp32 tile into smem (stride S134), 128 threads
__device__ __forceinline__ void load64x128(const float* __restrict__ g, int gstride,
                                           float* s, int tid) {
    #pragma unroll
    for (int it = 0; it < 16; ++it) {
        int f4 = tid + it * 128;
        int row = f4 >> 5, c4 = (f4 & 31) << 2;
        float4 v = *reinterpret_cast<const float4*>(g + (long)row * gstride + c4);
        float2* d = reinterpret_cast<float2*>(&s[row * S134 + c4]);
        d[0] = make_float2(v.x, v.y);
        d[1] = make_float2(v.z, v.w);
    }
}

// =====================================================================
// Projection: out[r][h] = tanh( sum_d x[r][d]*W[h][d] + b[h] ), 64x128 tile/CTA
// =====================================================================
__global__ void __launch_bounds__(128, 2)
proj_kernel(const float* __restrict__ x, const float* __restrict__ W,
            const float* __restrict__ bias, int sel)
{
    extern __shared__ float sm[];
    float* x_s = sm;                   // 64 * 134
    float* w_s = sm + 64 * S134;       // 128 * 134
    int tid = threadIdx.x;
    int r0 = blockIdx.x * 64;

    load64x128(x + (long)r0 * DMODEL, DMODEL, x_s, tid);
    #pragma unroll
    for (int it = 0; it < 32; ++it) {          // W: 128 x 128
        int f4 = tid + it * 128;
        int row = f4 >> 5, c4 = (f4 & 31) << 2;
        float4 v = *reinterpret_cast<const float4*>(W + (long)row * DMODEL + c4);
        float2* d = reinterpret_cast<float2*>(&w_s[row * S134 + c4]);
        d[0] = make_float2(v.x, v.y);
        d[1] = make_float2(v.z, v.w);
    }
    __syncthreads();

    int ty = tid >> 4, tx = tid & 15;          // 8 row-groups x 16 col-groups

    u64 acc[8][8] = {};
    #pragma unroll 4
    for (int dp = 0; dp < 64; ++dp) {          // d pairs
        u64 a[8], w[8];
        #pragma unroll
        for (int i = 0; i < 8; ++i) a[i] = lds_pair(&x_s[(ty*8 + i) * S134 + 2*dp]);
        #pragma unroll
        for (int j = 0; j < 8; ++j) w[j] = lds_pair(&w_s[(tx + j*16) * S134 + 2*dp]);
        #pragma unroll
        for (int i = 0; i < 8; ++i)
            #pragma unroll
            for (int j = 0; j < 8; ++j)
                ffma2(acc[i][j], a[i], w[j]);
    }

    float* outp = (sel == 0) ? g_q : (sel == 1) ? g_k : g_v;
    #pragma unroll
    for (int j = 0; j < 8; ++j) {
        int h = tx + j * 16;
        float bh = __ldg(&bias[h]);
        #pragma unroll
        for (int i = 0; i < 8; ++i) {
            int row = r0 + ty * 8 + i;
            float lo, hi; unpack2(acc[i][j], lo, hi);
            outp[(long)row * DMODEL + h] = tanh_fast(lo + hi + bh);
        }
    }
}

// =====================================================================
// Attention: per (batch, 64-query tile), stream 64-key blocks.
//   S = q k^T (FFMA2 pairs along d); p = mask ? exp(S) : 0 (no max-sub:
//   scores bounded << 88, masked lanes exact 0 -> identical to stable
//   softmax); O += p V (FFMA2 pairs along output h -> V needs no
//   transpose). Final O /= rowsum.
// =====================================================================
__global__ void __launch_bounds__(128, 2)
attn_kernel(const int* __restrict__ mask, float* __restrict__ out)
{
    extern __shared__ float sm[];
    float* q_s  = sm;                    // 64*134
    float* kv_s = q_s  + 64 * S134;      // 64*134 (k, then reused for v)
    float* p_s  = kv_s + 64 * S134;      // 64*66
    float* m_sf = p_s  + 64 * SP66;      // 64*66 (ints)
    float* red  = m_sf + 64 * SP66;      // 64*17
    float* rsum = red  + 64 * 17;        // 64
    int*   m_s  = (int*)m_sf;

    int tid = threadIdx.x;
    int b   = blockIdx.y;
    int q0  = blockIdx.x * 64;
    int ty  = tid >> 4, tx = tid & 15;

    load64x128(g_q + ((long)b * SEQ + q0) * DMODEL, DMODEL, q_s, tid);

    u64   oacc[8][4] = {};
    float rs[8] = {0,0,0,0,0,0,0,0};

    for (int jb = 0; jb < 16; ++jb) {
        int j0 = jb * 64;
        __syncthreads();   // prev GEMM2 done reading kv_s/p_s (iter 0: q_s visible)

        // load k tile
        load64x128(g_k + ((long)b * SEQ + j0) * DMODEL, DMODEL, kv_s, tid);
        // load mask tile: 64 rows x 64 ints (FIX: 64-wide addressing, 8 iters)
        {
            const int* mg = mask + ((long)b * SEQ + q0) * SEQ + j0;
            #pragma unroll
            for (int it = 0; it < 8; ++it) {
                int f4 = tid + it * 128;        // [0, 1024): 64 rows x 16 quad-groups
                int row = f4 >> 4, c4 = (f4 & 15) << 2;
                int4 v = *reinterpret_cast<const int4*>(mg + (long)row * SEQ + c4);
                int* d = &m_s[row * SP66 + c4];
                d[0] = v.x; d[1] = v.y; d[2] = v.z; d[3] = v.w;
            }
        }
        __syncthreads();

        // ---- GEMM1: S(64x64) = q(64x128) . k(64x128)^T ----
        u64 sacc[8][4] = {};
        #pragma unroll 4
        for (int dp = 0; dp < 64; ++dp) {
            u64 a[8], kk[4];
            #pragma unroll
            for (int i = 0; i < 8; ++i) a[i]  = lds_pair(&q_s [(ty*8 + i ) * S134 + 2*dp]);
            #pragma unroll
            for (int j = 0; j < 4; ++j) kk[j] = lds_pair(&kv_s[(tx + j*16) * S134 + 2*dp]);
            #pragma unroll
            for (int i = 0; i < 8; ++i)
                #pragma unroll
                for (int j = 0; j < 4; ++j)
                    ffma2(sacc[i][j], a[i], kk[j]);
        }
        // mask + exp + stage P, accumulate row partial sums
        #pragma unroll
        for (int i = 0; i < 8; ++i) {
            int row = ty * 8 + i;
            #pragma unroll
            for (int j = 0; j < 4; ++j) {
                int col = tx + j * 16;
                float lo, hi; unpack2(sacc[i][j], lo, hi);
                float s = lo + hi;
                float p = (m_s[row * SP66 + col] != 0) ? __expf(s) : 0.0f;
                rs[i] += p;
                p_s[row * SP66 + col] = p;
            }
        }
        __syncthreads();   // GEMM1 done with kv_s; p_s complete

        // load v tile into kv_s
        load64x128(g_v + ((long)b * SEQ + j0) * DMODEL, DMODEL, kv_s, tid);
        __syncthreads();

        // ---- GEMM2: O(64x128) += P(64x64) . V(64x128) ----
        #pragma unroll 2
        for (int jp = 0; jp < 32; ++jp) {
            u64 pd0[8], pd1[8];
            #pragma unroll
            for (int i = 0; i < 8; ++i) {
                float2 pp = *reinterpret_cast<const float2*>(&p_s[(ty*8 + i) * SP66 + 2*jp]);
                pd0[i] = pack2(pp.x, pp.x);
                pd1[i] = pack2(pp.y, pp.y);
            }
            u64 v0[4], v1[4];
            #pragma unroll
            for (int j = 0; j < 4; ++j) {
                int hp2 = 2 * (tx + j * 16);
                v0[j] = lds_pair(&kv_s[(2*jp    ) * S134 + hp2]);
                v1[j] = lds_pair(&kv_s[(2*jp + 1) * S134 + hp2]);
            }
            #pragma unroll
            for (int i = 0; i < 8; ++i)
                #pragma unroll
                for (int j = 0; j < 4; ++j) {
                    ffma2(oacc[i][j], pd0[i], v0[j]);
                    ffma2(oacc[i][j], pd1[i], v1[j]);
                }
        }
    }

    // rowsum reduction across the 16 col-thread partials
    __syncthreads();
    #pragma unroll
    for (int i = 0; i < 8; ++i) red[(ty*8 + i) * 17 + tx] = rs[i];
    __syncthreads();
    if (tid < 64) {
        float s = 0.0f;
        #pragma unroll
        for (int t = 0; t < 16; ++t) s += red[tid * 17 + t];
        rsum[tid] = s;
    }
    __syncthreads();

    #pragma unroll
    for (int i = 0; i < 8; ++i) {
        int row = ty * 8 + i;
        float inv = __fdividef(1.0f, rsum[row]);
        #pragma unroll
        for (int j = 0; j < 4; ++j) {
            float lo, hi; unpack2(oacc[i][j], lo, hi);
            float2 o = make_float2(lo * inv, hi * inv);
            *reinterpret_cast<float2*>(
                &out[((long)b * SEQ + q0 + row) * DMODEL + 2 * (tx + j * 16)]) = o;
        }
    }
}

// =====================================================================
extern "C" void kernel_launch(void* const* d_in, const int* in_sizes, int n_in,
                              void* d_out, int out_size)
{
    const float* x    = (const float*)d_in[0];
    const int*   mask = (const int*)  d_in[1];
    const float* Wv   = (const float*)d_in[2];
    const float* bv   = (const float*)d_in[3];
    const float* Wk   = (const float*)d_in[4];
    const float* bk   = (const float*)d_in[5];
    const float* Wq   = (const float*)d_in[6];
    const float* bq   = (const float*)d_in[7];
    float* out = (float*)d_out;

    int smem_proj = (64 * S134 + 128 * S134) * (int)sizeof(float);                 // ~100.5 KB
    int smem_attn = (64*S134 + 64*S134 + 64*SP66 + 64*SP66 + 64*17 + 64)
                    * (int)sizeof(float);                                          // ~104.5 KB
    cudaFuncSetAttribute(proj_kernel, cudaFuncAttributeMaxDynamicSharedMemorySize, smem_proj);
    cudaFuncSetAttribute(attn_kernel, cudaFuncAttributeMaxDynamicSharedMemorySize, smem_attn);

    // 65536 rows / 64 per CTA = 1024 CTAs per projection
    proj_kernel<<<1024, 128, smem_proj>>>(x, Wq, bq, 0);
    proj_kernel<<<1024, 128, smem_proj>>>(x, Wk, bk, 1);
    proj_kernel<<<1024, 128, smem_proj>>>(x, Wv, bv, 2);

    attn_kernel<<<dim3(16, BATCH), 128, smem_attn>>>(mask, out);
}

// round 9
// speedup vs baseline: 1.7159x; 1.7159x over previous
#include <cuda_runtime.h>
#include <cuda_bf16.h>

typedef unsigned int u32;
typedef unsigned short u16;
typedef unsigned long long u64;

#define BATCH 64
#define SEQ   1024
#define DM    128
#define S134  134
#define DEVINL __device__ __forceinline__

// bf16 hi/lo split scratch, packed pairs as u32 (low half = even index)
__device__ u32 g_q_hi[BATCH*SEQ*64];
__device__ u32 g_q_lo[BATCH*SEQ*64];
__device__ u32 g_k_hi[BATCH*SEQ*64];
__device__ u32 g_k_lo[BATCH*SEQ*64];
__device__ u32 g_vt_hi[BATCH*DM*512];   // [b][h][j/2]
__device__ u32 g_vt_lo[BATCH*DM*512];

// ---------------- helpers ----------------
DEVINL void ffma2(u64 &d, u64 a, u64 b){ asm("fma.rn.f32x2 %0, %1, %2, %0;" : "+l"(d) : "l"(a), "l"(b)); }
DEVINL void unpack2(u64 v, float &x, float &y){ asm("mov.b64 {%0, %1}, %2;" : "=f"(x), "=f"(y) : "l"(v)); }
DEVINL u64  lds_pair(const float* p){ return *reinterpret_cast<const u64*>(p); }
DEVINL float tanh_fast(float x){
    float ax = fminf(fabsf(x), 20.0f);
    float e  = __expf(2.0f*ax);
    return copysignf(__fdividef(e-1.0f, e+1.0f), x);
}
// pack two fp32 -> bf16x2 (low = e0)
DEVINL u32 bfpair(float e0, float e1){ u32 r; asm("cvt.rn.bf16x2.f32 %0, %1, %2;":"=r"(r):"f"(e1),"f"(e0)); return r; }
DEVINL float bflo_f(u32 p){ return __uint_as_float(p<<16); }
DEVINL float bfhi_f(u32 p){ return __uint_as_float(p & 0xFFFF0000u); }
DEVINL void split2(float e0, float e1, u32 &hi, u32 &lo){
    hi = bfpair(e0, e1);
    lo = bfpair(e0 - bflo_f(hi), e1 - bfhi_f(hi));
}
// mma.sync m16n8k16 bf16 (compute_103-legal, lowers to HMMA.16816)
DEVINL void mma16816(float* c, u32 a0,u32 a1,u32 a2,u32 a3, u32 b0,u32 b1){
    asm volatile("mma.sync.aligned.m16n8k16.row.col.f32.bf16.bf16.f32 "
        "{%0,%1,%2,%3}, {%4,%5,%6,%7}, {%8,%9}, {%0,%1,%2,%3};"
        : "+f"(c[0]),"+f"(c[1]),"+f"(c[2]),"+f"(c[3])
        : "r"(a0),"r"(a1),"r"(a2),"r"(a3),"r"(b0),"r"(b1));
}

// =====================================================================
// Projection (FFMA2): y = tanh(xW^T + b); writes pre-split bf16 pairs.
// Thread cols: h_j = 2*tx + (j&1) + 32*(j>>1)  (adjacent h pairs per thread)
// =====================================================================
__global__ void __launch_bounds__(128, 2)
proj_kernel(const float* __restrict__ x, const float* __restrict__ W,
            const float* __restrict__ bias, int sel)
{
    extern __shared__ float smf[];
    float* x_s = smf;
    float* w_s = smf + 64 * S134;
    int tid = threadIdx.x;
    int r0 = blockIdx.x * 64;

    #pragma unroll
    for (int it = 0; it < 16; ++it) {
        int f4 = tid + it*128, row = f4>>5, c4 = (f4&31)<<2;
        float4 v = *reinterpret_cast<const float4*>(x + (long)(r0+row)*DM + c4);
        float2* d = reinterpret_cast<float2*>(&x_s[row*S134 + c4]);
        d[0] = make_float2(v.x,v.y); d[1] = make_float2(v.z,v.w);
    }
    #pragma unroll
    for (int it = 0; it < 32; ++it) {
        int f4 = tid + it*128, row = f4>>5, c4 = (f4&31)<<2;
        float4 v = *reinterpret_cast<const float4*>(W + (long)row*DM + c4);
        float2* d = reinterpret_cast<float2*>(&w_s[row*S134 + c4]);
        d[0] = make_float2(v.x,v.y); d[1] = make_float2(v.z,v.w);
    }
    __syncthreads();

    int ty = tid>>4, tx = tid&15;
    u64 acc[8][8] = {};
    #pragma unroll 4
    for (int dp = 0; dp < 64; ++dp) {
        u64 a[8], w[8];
        #pragma unroll
        for (int i=0;i<8;++i) a[i] = lds_pair(&x_s[(ty*8+i)*S134 + 2*dp]);
        #pragma unroll
        for (int j=0;j<8;++j) {
            int hj = 2*tx + (j&1) + 32*(j>>1);
            w[j] = lds_pair(&w_s[hj*S134 + 2*dp]);
        }
        #pragma unroll
        for (int i=0;i<8;++i)
            #pragma unroll
            for (int j=0;j<8;++j) ffma2(acc[i][j], a[i], w[j]);
    }

    // y values per (i, j): col h_j
    float y[8][8];
    #pragma unroll
    for (int j=0;j<8;++j) {
        int hj = 2*tx + (j&1) + 32*(j>>1);
        float bh = __ldg(&bias[hj]);
        #pragma unroll
        for (int i=0;i<8;++i) {
            float lo,hi; unpack2(acc[i][j],lo,hi);
            y[i][j] = tanh_fast(lo+hi+bh);
        }
    }

    if (sel < 2) {
        u32* gh = (sel==0)? g_q_hi : g_k_hi;
        u32* gl = (sel==0)? g_q_lo : g_k_lo;
        #pragma unroll
        for (int i=0;i<8;++i) {
            long row = r0 + ty*8 + i;
            #pragma unroll
            for (int jj=0;jj<4;++jj) {
                u32 h2,l2; split2(y[i][2*jj], y[i][2*jj+1], h2, l2);
                gh[row*64 + 16*jj + tx] = h2;
                gl[row*64 + 16*jj + tx] = l2;
            }
        }
    } else {
        int b  = r0 >> 10;
        int n0 = (r0 & 1023) + ty*8;
        #pragma unroll
        for (int j=0;j<8;++j) {
            int hj = 2*tx + (j&1) + 32*(j>>1);
            u32 hw[4], lw[4];
            #pragma unroll
            for (int i2=0;i2<4;++i2) split2(y[2*i2][j], y[2*i2+1][j], hw[i2], lw[i2]);
            long base = ((long)(b*DM + hj))*512 + (n0>>1);
            *(uint4*)&g_vt_hi[base] = make_uint4(hw[0],hw[1],hw[2],hw[3]);
            *(uint4*)&g_vt_lo[base] = make_uint4(lw[0],lw[1],lw[2],lw[3]);
        }
    }
}

// =====================================================================
// Attention (mma.sync bf16, 3-term split): CTA = 128 q-rows, 8 warps,
// warp w owns q rows [16w,16w+16). 16 key-blocks of 64.
// =====================================================================
#define KS_STRIDE 68    // u32 stride
#define VT_STRIDE 36
#define A_K_HI   0
#define A_K_LO   (A_K_HI + 64*KS_STRIDE*4)
#define A_VT_HI  (A_K_LO + 64*KS_STRIDE*4)
#define A_VT_LO  (A_VT_HI + 128*VT_STRIDE*4)
#define A_MASK   (A_VT_LO + 128*VT_STRIDE*4)
#define A_SMEM   (A_MASK + 128*68)

__global__ void __launch_bounds__(256, 1)
attn_kernel(const int* __restrict__ mask, float* __restrict__ out)
{
    extern __shared__ char sm[];
    u32* ks_hi = (u32*)(sm + A_K_HI);
    u32* ks_lo = (u32*)(sm + A_K_LO);
    u32* vs_hi = (u32*)(sm + A_VT_HI);
    u32* vs_lo = (u32*)(sm + A_VT_LO);
    u32* ms_w  = (u32*)(sm + A_MASK);

    int tid = threadIdx.x, wid = tid>>5, lane = tid&31;
    int g = lane>>2, tig = lane&3;
    int b  = blockIdx.y;
    int q0 = blockIdx.x * 128;
    int rowg  = wid*16 + g;        // this thread's first q row (c0/c1)
    long grow0 = (long)(b*SEQ + q0 + rowg);

    // ---- load Q fragments (persist in registers): rows rowg, rowg+8 ----
    u32 aqh[2][16], aql[2][16];
    {
        const u32* qh0 = g_q_hi + grow0*64;
        const u32* ql0 = g_q_lo + grow0*64;
        const u32* qh1 = qh0 + 8*64;
        const u32* ql1 = ql0 + 8*64;
        #pragma unroll
        for (int t=0;t<16;++t) {
            int c = 4*t + tig;
            aqh[0][t] = __ldg(&qh0[c]);  aqh[1][t] = __ldg(&qh1[c]);
            aql[0][t] = __ldg(&ql0[c]);  aql[1][t] = __ldg(&ql1[c]);
        }
    }

    float oc[16][4];
    #pragma unroll
    for (int n=0;n<16;++n) { oc[n][0]=0; oc[n][1]=0; oc[n][2]=0; oc[n][3]=0; }
    float rs0 = 0.0f, rs1 = 0.0f;

    for (int jb = 0; jb < 16; ++jb) {
        int j0 = jb * 64;
        __syncthreads();   // previous block done reading smem

        // ---- stage k (64x128), vt (128x64), mask (128x64) ----
        {
            const uint4* gk_h = (const uint4*)(g_k_hi + (long)(b*SEQ + j0)*64);
            const uint4* gk_l = (const uint4*)(g_k_lo + (long)(b*SEQ + j0)*64);
            #pragma unroll
            for (int p=0;p<4;++p) {          // 1024 uint4 over 256 thr
                int i = tid + p*256, row = i>>4, c4 = (i&15)*4;
                *(uint4*)&ks_hi[row*KS_STRIDE + c4] = __ldg(&gk_h[i]);
                *(uint4*)&ks_lo[row*KS_STRIDE + c4] = __ldg(&gk_l[i]);
            }
            // V^T slice: per h row, uint4 index (j0>>3)..(j0>>3)+7  (FIX)
            const uint4* gv_h = (const uint4*)(g_vt_hi + (long)(b*DM)*512);
            const uint4* gv_l = (const uint4*)(g_vt_lo + (long)(b*DM)*512);
            #pragma unroll
            for (int p=0;p<4;++p) {          // 128 h rows x 8 uint4 (32 u32 = 64 j)
                int i = tid + p*256, row = i>>3, c4 = (i&7)*4;
                int src = row*128 + (j0>>3) + (c4>>2);
                *(uint4*)&vs_hi[row*VT_STRIDE + c4] = __ldg(&gv_h[src]);
                *(uint4*)&vs_lo[row*VT_STRIDE + c4] = __ldg(&gv_l[src]);
            }
            const int* mg = mask + ((long)(b*SEQ + q0))*SEQ + j0;
            #pragma unroll
            for (int p=0;p<8;++p) {          // 2048 int4 over 256 thr
                int i = tid + p*256, row = i>>4, c16 = (i&15);
                int4 m4 = __ldg((const int4*)(mg + (long)row*SEQ + 4*c16));
                u32 pk = (m4.x?1u:0u) | (m4.y?0x100u:0u) | (m4.z?0x10000u:0u) | (m4.w?0x1000000u:0u);
                ms_w[row*17 + c16] = pk;
            }
        }
        __syncthreads();

        // ---- QK: S(16x64 per warp) = q . k^T, 3-term split ----
        float sc[8][4];
        #pragma unroll
        for (int n=0;n<8;++n){ sc[n][0]=0; sc[n][1]=0; sc[n][2]=0; sc[n][3]=0; }
        #pragma unroll
        for (int n=0;n<8;++n) {
            int key = 8*n + g;
            #pragma unroll
            for (int ks=0;ks<8;++ks) {
                u32 bh0 = ks_hi[key*KS_STRIDE + 8*ks + tig];
                u32 bh1 = ks_hi[key*KS_STRIDE + 8*ks + 4 + tig];
                u32 bl0 = ks_lo[key*KS_STRIDE + 8*ks + tig];
                u32 bl1 = ks_lo[key*KS_STRIDE + 8*ks + 4 + tig];
                mma16816(sc[n], aqh[0][2*ks], aqh[1][2*ks], aqh[0][2*ks+1], aqh[1][2*ks+1], bh0, bh1);
                mma16816(sc[n], aqh[0][2*ks], aqh[1][2*ks], aqh[0][2*ks+1], aqh[1][2*ks+1], bl0, bl1);
                mma16816(sc[n], aql[0][2*ks], aql[1][2*ks], aql[0][2*ks+1], aql[1][2*ks+1], bh0, bh1);
            }
        }

        // ---- mask + exp (in-register softmax numerator) ----
        const char* mrow0 = sm + A_MASK + rowg*68;
        const char* mrow1 = mrow0 + 8*68;
        #pragma unroll
        for (int n=0;n<8;++n) {
            int col = 8*n + 2*tig;
            u32 ma = *(const u16*)(mrow0 + col);
            u32 mb = *(const u16*)(mrow1 + col);
            float p0 = (ma & 0xFF)? __expf(sc[n][0]) : 0.0f;
            float p1 = (ma >> 8) ? __expf(sc[n][1]) : 0.0f;
            float p2 = (mb & 0xFF)? __expf(sc[n][2]) : 0.0f;
            float p3 = (mb >> 8) ? __expf(sc[n][3]) : 0.0f;
            rs0 += p0 + p1;  rs1 += p2 + p3;
            sc[n][0]=p0; sc[n][1]=p1; sc[n][2]=p2; sc[n][3]=p3;
        }

        // ---- PV: O(16x128) += P(16x64) . V^T, P split in-register ----
        #pragma unroll
        for (int ks=0;ks<4;++ks) {
            u32 ah[4], al[4];
            split2(sc[2*ks  ][0], sc[2*ks  ][1], ah[0], al[0]);
            split2(sc[2*ks  ][2], sc[2*ks  ][3], ah[1], al[1]);
            split2(sc[2*ks+1][0], sc[2*ks+1][1], ah[2], al[2]);
            split2(sc[2*ks+1][2], sc[2*ks+1][3], ah[3], al[3]);
            #pragma unroll
            for (int n=0;n<16;++n) {
                int h = 8*n + g;
                u32 bh0 = vs_hi[h*VT_STRIDE + 8*ks + tig];
                u32 bh1 = vs_hi[h*VT_STRIDE + 8*ks + 4 + tig];
                u32 bl0 = vs_lo[h*VT_STRIDE + 8*ks + tig];
                u32 bl1 = vs_lo[h*VT_STRIDE + 8*ks + 4 + tig];
                mma16816(oc[n], ah[0],ah[1],ah[2],ah[3], bh0, bh1);
                mma16816(oc[n], ah[0],ah[1],ah[2],ah[3], bl0, bl1);
                mma16816(oc[n], al[0],al[1],al[2],al[3], bh0, bh1);
            }
        }
    }

    // ---- row sums (quad reduce) + normalize + store ----
    rs0 += __shfl_xor_sync(0xFFFFFFFFu, rs0, 1);
    rs0 += __shfl_xor_sync(0xFFFFFFFFu, rs0, 2);
    rs1 += __shfl_xor_sync(0xFFFFFFFFu, rs1, 1);
    rs1 += __shfl_xor_sync(0xFFFFFFFFu, rs1, 2);
    float inv0 = __fdividef(1.0f, rs0);
    float inv1 = __fdividef(1.0f, rs1);

    float* o0 = out + grow0*DM;
    float* o1 = o0 + 8*DM;
    #pragma unroll
    for (int n=0;n<16;++n) {
        int col = 8*n + 2*tig;
        *(float2*)(o0 + col) = make_float2(oc[n][0]*inv0, oc[n][1]*inv0);
        *(float2*)(o1 + col) = make_float2(oc[n][2]*inv1, oc[n][3]*inv1);
    }
}

// =====================================================================
extern "C" void kernel_launch(void* const* d_in, const int* in_sizes, int n_in,
                              void* d_out, int out_size)
{
    const float* x    = (const float*)d_in[0];
    const int*   mask = (const int*)  d_in[1];
    const float* Wv   = (const float*)d_in[2];
    const float* bv   = (const float*)d_in[3];
    const float* Wk   = (const float*)d_in[4];
    const float* bk   = (const float*)d_in[5];
    const float* Wq   = (const float*)d_in[6];
    const float* bq   = (const float*)d_in[7];
    float* out = (float*)d_out;

    int smem_proj = (64*S134 + 128*S134) * (int)sizeof(float);
    cudaFuncSetAttribute(proj_kernel, cudaFuncAttributeMaxDynamicSharedMemorySize, smem_proj);
    cudaFuncSetAttribute(attn_kernel, cudaFuncAttributeMaxDynamicSharedMemorySize, A_SMEM);

    proj_kernel<<<1024, 128, smem_proj>>>(x, Wq, bq, 0);
    proj_kernel<<<1024, 128, smem_proj>>>(x, Wk, bk, 1);
    proj_kernel<<<1024, 128, smem_proj>>>(x, Wv, bv, 2);

    attn_kernel<<<dim3(SEQ/128, BATCH), 256, A_SMEM>>>(mask, out);
}

// round 11
// speedup vs baseline: 2.1837x; 1.2726x over previous
#include <cuda_runtime.h>
#include <cuda_bf16.h>

typedef unsigned int u32;
typedef unsigned short u16;
typedef unsigned long long u64;

#define BATCH 64
#define SEQ   1024
#define DM    128
#define DEVINL __device__ __forceinline__

// bf16 hi/lo split scratch, packed pairs as u32 (low half = even index)
__device__ u32 g_q_hi[BATCH*SEQ*64];
__device__ u32 g_q_lo[BATCH*SEQ*64];
__device__ u32 g_k_hi[BATCH*SEQ*64];
__device__ u32 g_k_lo[BATCH*SEQ*64];
__device__ u32 g_vt_hi[BATCH*DM*512];   // [b][h][j/2]
__device__ u32 g_vt_lo[BATCH*DM*512];

// ---------------- helpers ----------------
DEVINL float tanh_fast(float x){
    float ax = fminf(fabsf(x), 20.0f);
    float e  = __expf(2.0f*ax);
    return copysignf(__fdividef(e-1.0f, e+1.0f), x);
}
DEVINL u32 bfpair(float e0, float e1){ u32 r; asm("cvt.rn.bf16x2.f32 %0, %1, %2;":"=r"(r):"f"(e1),"f"(e0)); return r; }
DEVINL float bflo_f(u32 p){ return __uint_as_float(p<<16); }
DEVINL float bfhi_f(u32 p){ return __uint_as_float(p & 0xFFFF0000u); }
DEVINL void split2(float e0, float e1, u32 &hi, u32 &lo){
    hi = bfpair(e0, e1);
    lo = bfpair(e0 - bflo_f(hi), e1 - bfhi_f(hi));
}
DEVINL void mma16816(float* c, u32 a0,u32 a1,u32 a2,u32 a3, u32 b0,u32 b1){
    asm volatile("mma.sync.aligned.m16n8k16.row.col.f32.bf16.bf16.f32 "
        "{%0,%1,%2,%3}, {%4,%5,%6,%7}, {%8,%9}, {%0,%1,%2,%3};"
        : "+f"(c[0]),"+f"(c[1]),"+f"(c[2]),"+f"(c[3])
        : "r"(a0),"r"(a1),"r"(a2),"r"(a3),"r"(b0),"r"(b1));
}
DEVINL u32 sm_u32(const void* p){ u32 a; asm("{ .reg .u64 t; cvta.to.shared.u64 t, %1; cvt.u32.u64 %0, t; }":"=r"(a):"l"(p)); return a; }
DEVINL void cp16(u32 dst, const void* src){
    asm volatile("cp.async.cg.shared.global [%0], [%1], 16;"::"r"(dst),"l"(src):"memory");
}
#define CP_COMMIT() asm volatile("cp.async.commit_group;":::"memory")
#define CP_WAIT1()  asm volatile("cp.async.wait_group 1;":::"memory")
#define CP_WAIT0()  asm volatile("cp.async.wait_group 0;":::"memory")

// =====================================================================
// Fused tensorized projections: one CTA = 128 rows; x fragments loaded
// from gmem and hi/lo-split ONCE in registers, reused for Wq, Wk, Wv.
// =====================================================================
#define PW_STRIDE 68      // u32
#define PW_HI     0       // 128*68
#define PW_LO     8704
#define P_SMEM_BYTES (17408*4)   // 69,632 (y_s transpose scratch reuses it: 128*130*4=66,560)

__global__ void __launch_bounds__(256, 1)
proj_tc_kernel(const float* __restrict__ x,
               const float* __restrict__ Wq, const float* __restrict__ bq,
               const float* __restrict__ Wk, const float* __restrict__ bk,
               const float* __restrict__ Wv, const float* __restrict__ bv)
{
    extern __shared__ char smc[];
    u32* ws_hi = (u32*)smc + PW_HI;
    u32* ws_lo = (u32*)smc + PW_LO;

    int tid = threadIdx.x, wid = tid>>5, lane = tid&31;
    int g = lane>>2, tig = lane&3;
    int r0 = blockIdx.x * 128;
    int b  = r0 >> 10;
    int rowg = wid*16 + g;
    long grow0 = (long)(r0 + rowg);

    // ---- x fragments: rows rowg, rowg+8; split in registers, persist ----
    u32 axh[2][16], axl[2][16];
    #pragma unroll
    for (int r2=0;r2<2;++r2){
        const float* xr = x + (grow0 + 8*r2)*DM;
        #pragma unroll
        for (int t=0;t<16;++t){
            float2 v = __ldg((const float2*)(xr + 8*t + 2*tig));
            split2(v.x, v.y, axh[r2][t], axl[r2][t]);
        }
    }

    #pragma unroll 1
    for (int sel=0; sel<3; ++sel){
        const float* W    = (sel==0)? Wq : (sel==1)? Wk : Wv;
        const float* bias = (sel==0)? bq : (sel==1)? bk : bv;

        __syncthreads();   // prior sel done reading ws
        #pragma unroll
        for (int p=0;p<16;++p){
            int i = tid + p*256, row = i>>5, c4 = (i&31)*4;
            float4 wv = __ldg((const float4*)(W + (long)row*DM + c4));
            u32 h0,l0,h1,l1;
            split2(wv.x, wv.y, h0, l0);
            split2(wv.z, wv.w, h1, l1);
            *(u64*)(ws_hi + row*PW_STRIDE + (c4>>1)) = ((u64)h1<<32)|h0;
            *(u64*)(ws_lo + row*PW_STRIDE + (c4>>1)) = ((u64)l1<<32)|l0;
        }
        __syncthreads();

        float oc[16][4];
        #pragma unroll
        for (int n=0;n<16;++n){ oc[n][0]=0; oc[n][1]=0; oc[n][2]=0; oc[n][3]=0; }
        #pragma unroll
        for (int n=0;n<16;++n){
            int h = 8*n + g;
            #pragma unroll
            for (int ks=0;ks<8;++ks){
                u32 bh0 = ws_hi[h*PW_STRIDE + 8*ks + tig];
                u32 bh1 = ws_hi[h*PW_STRIDE + 8*ks + 4 + tig];
                u32 bl0 = ws_lo[h*PW_STRIDE + 8*ks + tig];
                u32 bl1 = ws_lo[h*PW_STRIDE + 8*ks + 4 + tig];
                mma16816(oc[n], axh[0][2*ks], axh[1][2*ks], axh[0][2*ks+1], axh[1][2*ks+1], bh0, bh1);
                mma16816(oc[n], axh[0][2*ks], axh[1][2*ks], axh[0][2*ks+1], axh[1][2*ks+1], bl0, bl1);
                mma16816(oc[n], axl[0][2*ks], axl[1][2*ks], axl[0][2*ks+1], axl[1][2*ks+1], bh0, bh1);
            }
        }

        if (sel < 2){
            u32* gh = (sel==0)? g_q_hi : g_k_hi;
            u32* gl = (sel==0)? g_q_lo : g_k_lo;
            #pragma unroll
            for (int n=0;n<16;++n){
                float2 b2 = __ldg((const float2*)(bias + 8*n + 2*tig));
                float y0 = tanh_fast(oc[n][0] + b2.x);
                float y1 = tanh_fast(oc[n][1] + b2.y);
                float y2 = tanh_fast(oc[n][2] + b2.x);
                float y3 = tanh_fast(oc[n][3] + b2.y);
                u32 h2,l2;
                split2(y0,y1,h2,l2);
                gh[grow0*64 + 4*n + tig] = h2;  gl[grow0*64 + 4*n + tig] = l2;
                split2(y2,y3,h2,l2);
                gh[(grow0+8)*64 + 4*n + tig] = h2;  gl[(grow0+8)*64 + 4*n + tig] = l2;
            }
        } else {
            // V: transpose through smem -> g_vt[b][h][j/2]
            __syncthreads();   // all warps done reading ws (about to overwrite)
            float* y_s = (float*)smc;    // [h][row], stride 130
            #pragma unroll
            for (int n=0;n<16;++n){
                float2 b2 = __ldg((const float2*)(bias + 8*n + 2*tig));
                int col = 8*n + 2*tig;
                y_s[(col  )*130 + rowg    ] = tanh_fast(oc[n][0] + b2.x);
                y_s[(col+1)*130 + rowg    ] = tanh_fast(oc[n][1] + b2.y);
                y_s[(col  )*130 + rowg + 8] = tanh_fast(oc[n][2] + b2.x);
                y_s[(col+1)*130 + rowg + 8] = tanh_fast(oc[n][3] + b2.y);
            }
            __syncthreads();
            int h = tid >> 1;
            int phalf = (tid & 1) * 32;
            long gbase = ((long)(b*DM + h))*512 + ((r0 & 1023) >> 1) + phalf;
            #pragma unroll
            for (int ck=0; ck<8; ++ck){
                u32 hw[4], lw[4];
                #pragma unroll
                for (int q2=0;q2<4;++q2){
                    int p2 = phalf + ck*4 + q2;
                    float2 yy = *(const float2*)(y_s + h*130 + 2*p2);
                    split2(yy.x, yy.y, hw[q2], lw[q2]);
                }
                *(uint4*)(g_vt_hi + gbase + ck*4) = make_uint4(hw[0],hw[1],hw[2],hw[3]);
                *(uint4*)(g_vt_lo + gbase + ck*4) = make_uint4(lw[0],lw[1],lw[2],lw[3]);
            }
        }
    }
}

// =====================================================================
// Attention (mma.sync bf16, 3-term split) + cp.async double buffering.
// CTA = 128 q-rows, 8 warps; 16 key-blocks of 64.
// =====================================================================
#define KS_STRIDE 68
#define VT_STRIDE 36
// per-buffer u32 offsets
#define OF_KH 0
#define OF_KL 4352
#define OF_VH 8704
#define OF_VL 13312
#define OF_MS 17920
#define BUF_U32 26624
#define A_SMEM (2*BUF_U32*4)   // 212,992 B

__global__ void __launch_bounds__(256, 1)
attn_kernel(const int* __restrict__ mask, float* __restrict__ out)
{
    extern __shared__ char smc[];
    u32* smp = (u32*)smc;
    u32  sb  = sm_u32(smc);

    int tid = threadIdx.x, wid = tid>>5, lane = tid&31;
    int g = lane>>2, tig = lane&3;
    int b  = blockIdx.y;
    int q0 = blockIdx.x * 128;
    int rowg  = wid*16 + g;
    long grow0 = (long)(b*SEQ + q0 + rowg);

    const uint4* gk_h = (const uint4*)(g_k_hi + (long)(b*SEQ)*64);
    const uint4* gk_l = (const uint4*)(g_k_lo + (long)(b*SEQ)*64);
    const uint4* gv_h = (const uint4*)(g_vt_hi + (long)(b*DM)*512);
    const uint4* gv_l = (const uint4*)(g_vt_lo + (long)(b*DM)*512);
    const int*   mg   = mask + ((long)(b*SEQ + q0))*SEQ;

    // ---- Q fragments (persist): rows rowg, rowg+8 ----
    u32 aqh[2][16], aql[2][16];
    {
        const u32* qh0 = g_q_hi + grow0*64;
        const u32* ql0 = g_q_lo + grow0*64;
        #pragma unroll
        for (int t=0;t<16;++t){
            int c = 4*t + tig;
            aqh[0][t] = __ldg(&qh0[c]);  aqh[1][t] = __ldg(&qh0[8*64 + c]);
            aql[0][t] = __ldg(&ql0[c]);  aql[1][t] = __ldg(&ql0[8*64 + c]);
        }
    }

    // ---- staging via cp.async into buffer `bi` for key block jb ----
    auto stage = [&](int jb, int bi){
        u32 base = sb + (u32)(bi*BUF_U32*4);
        int j0 = jb*64;
        #pragma unroll
        for (int p=0;p<4;++p){                 // K: 64 rows x 16 uint4 (hi+lo)
            int i = tid + p*256, row = i>>4, c4 = (i&15)*4;
            int gi = j0*16 + i;                // FIX: row j0+row, 16 uint4/row
            cp16(base + (OF_KH + row*KS_STRIDE + c4)*4, gk_h + gi);
            cp16(base + (OF_KL + row*KS_STRIDE + c4)*4, gk_l + gi);
        }
        #pragma unroll
        for (int p=0;p<4;++p){                 // V^T: 128 rows x 8 uint4 (hi+lo)
            int i = tid + p*256, row = i>>3, c4 = (i&7)*4;
            int src = row*128 + (j0>>3) + (c4>>2);
            cp16(base + (OF_VH + row*VT_STRIDE + c4)*4, gv_h + src);
            cp16(base + (OF_VL + row*VT_STRIDE + c4)*4, gv_l + src);
        }
        #pragma unroll
        for (int p=0;p<8;++p){                 // mask raw: 128 rows x 16 uint4
            int i = tid + p*256, row = i>>4, c16 = (i&15);
            cp16(base + (OF_MS + row*KS_STRIDE + c16*4)*4,
                 (const uint4*)(mg + (long)row*SEQ + j0) + c16);
        }
    };

    float oc[16][4];
    #pragma unroll
    for (int n=0;n<16;++n){ oc[n][0]=0; oc[n][1]=0; oc[n][2]=0; oc[n][3]=0; }
    float rs0 = 0.0f, rs1 = 0.0f;

    stage(0, 0); CP_COMMIT();

    for (int jb = 0; jb < 16; ++jb) {
        __syncthreads();                       // compute jb-1 done -> buffer free
        if (jb < 15) { stage(jb+1, (jb+1)&1); CP_COMMIT(); CP_WAIT1(); }
        else         { CP_WAIT0(); }
        __syncthreads();                       // buffer jb visible to all

        u32* bp    = smp + (jb&1)*BUF_U32;
        u32* ks_hi = bp + OF_KH;
        u32* ks_lo = bp + OF_KL;
        u32* vs_hi = bp + OF_VH;
        u32* vs_lo = bp + OF_VL;
        const int* msB = (const int*)(bp + OF_MS);

        // ---- QK: S(16x64 per warp), 3-term split ----
        float sc[8][4];
        #pragma unroll
        for (int n=0;n<8;++n){ sc[n][0]=0; sc[n][1]=0; sc[n][2]=0; sc[n][3]=0; }
        #pragma unroll
        for (int n=0;n<8;++n){
            int key = 8*n + g;
            #pragma unroll
            for (int ks=0;ks<8;++ks){
                u32 bh0 = ks_hi[key*KS_STRIDE + 8*ks + tig];
                u32 bh1 = ks_hi[key*KS_STRIDE + 8*ks + 4 + tig];
                u32 bl0 = ks_lo[key*KS_STRIDE + 8*ks + tig];
                u32 bl1 = ks_lo[key*KS_STRIDE + 8*ks + 4 + tig];
                mma16816(sc[n], aqh[0][2*ks], aqh[1][2*ks], aqh[0][2*ks+1], aqh[1][2*ks+1], bh0, bh1);
                mma16816(sc[n], aqh[0][2*ks], aqh[1][2*ks], aqh[0][2*ks+1], aqh[1][2*ks+1], bl0, bl1);
                mma16816(sc[n], aql[0][2*ks], aql[1][2*ks], aql[0][2*ks+1], aql[1][2*ks+1], bh0, bh1);
            }
        }

        // ---- mask + exp ----
        const int* mrow0 = msB + rowg*KS_STRIDE;
        const int* mrow1 = mrow0 + 8*KS_STRIDE;
        #pragma unroll
        for (int n=0;n<8;++n){
            int col = 8*n + 2*tig;
            int2 ma = *(const int2*)(mrow0 + col);
            int2 mb2 = *(const int2*)(mrow1 + col);
            float p0 = ma.x  ? __expf(sc[n][0]) : 0.0f;
            float p1 = ma.y  ? __expf(sc[n][1]) : 0.0f;
            float p2 = mb2.x ? __expf(sc[n][2]) : 0.0f;
            float p3 = mb2.y ? __expf(sc[n][3]) : 0.0f;
            rs0 += p0 + p1;  rs1 += p2 + p3;
            sc[n][0]=p0; sc[n][1]=p1; sc[n][2]=p2; sc[n][3]=p3;
        }

        // ---- PV: O(16x128) += P(16x64) . V^T ----
        #pragma unroll
        for (int ks=0;ks<4;++ks){
            u32 ah[4], al[4];
            split2(sc[2*ks  ][0], sc[2*ks  ][1], ah[0], al[0]);
            split2(sc[2*ks  ][2], sc[2*ks  ][3], ah[1], al[1]);
            split2(sc[2*ks+1][0], sc[2*ks+1][1], ah[2], al[2]);
            split2(sc[2*ks+1][2], sc[2*ks+1][3], ah[3], al[3]);
            #pragma unroll
            for (int n=0;n<16;++n){
                int h = 8*n + g;
                u32 bh0 = vs_hi[h*VT_STRIDE + 8*ks + tig];
                u32 bh1 = vs_hi[h*VT_STRIDE + 8*ks + 4 + tig];
                u32 bl0 = vs_lo[h*VT_STRIDE + 8*ks + tig];
                u32 bl1 = vs_lo[h*VT_STRIDE + 8*ks + 4 + tig];
                mma16816(oc[n], ah[0],ah[1],ah[2],ah[3], bh0, bh1);
                mma16816(oc[n], ah[0],ah[1],ah[2],ah[3], bl0, bl1);
                mma16816(oc[n], al[0],al[1],al[2],al[3], bh0, bh1);
            }
        }
    }

    // ---- row sums (quad reduce) + normalize + store ----
    rs0 += __shfl_xor_sync(0xFFFFFFFFu, rs0, 1);
    rs0 += __shfl_xor_sync(0xFFFFFFFFu, rs0, 2);
    rs1 += __shfl_xor_sync(0xFFFFFFFFu, rs1, 1);
    rs1 += __shfl_xor_sync(0xFFFFFFFFu, rs1, 2);
    float inv0 = __fdividef(1.0f, rs0);
    float inv1 = __fdividef(1.0f, rs1);

    float* o0 = out + grow0*DM;
    float* o1 = o0 + 8*DM;
    #pragma unroll
    for (int n=0;n<16;++n){
        int col = 8*n + 2*tig;
        *(float2*)(o0 + col) = make_float2(oc[n][0]*inv0, oc[n][1]*inv0);
        *(float2*)(o1 + col) = make_float2(oc[n][2]*inv1, oc[n][3]*inv1);
    }
}

// =====================================================================
extern "C" void kernel_launch(void* const* d_in, const int* in_sizes, int n_in,
                              void* d_out, int out_size)
{
    const float* x    = (const float*)d_in[0];
    const int*   mask = (const int*)  d_in[1];
    const float* Wv   = (const float*)d_in[2];
    const float* bv   = (const float*)d_in[3];
    const float* Wk   = (const float*)d_in[4];
    const float* bk   = (const float*)d_in[5];
    const float* Wq   = (const float*)d_in[6];
    const float* bq   = (const float*)d_in[7];
    float* out = (float*)d_out;

    cudaFuncSetAttribute(proj_tc_kernel, cudaFuncAttributeMaxDynamicSharedMemorySize, P_SMEM_BYTES);
    cudaFuncSetAttribute(attn_kernel,    cudaFuncAttributeMaxDynamicSharedMemorySize, A_SMEM);

    proj_tc_kernel<<<512, 256, P_SMEM_BYTES>>>(x, Wq, bq, Wk, bk, Wv, bv);
    attn_kernel<<<dim3(SEQ/128, BATCH), 256, A_SMEM>>>(mask, out);
}